// round 4
// baseline (speedup 1.0000x reference)
#include <cuda_runtime.h>
#include <cstdint>

// ---------------- problem constants ----------------
namespace {
constexpr int B    = 2;
constexpr int C0   = 64;
constexpr int C1   = 128;
constexpr int H    = 128, W = 128;
constexpr int HW   = H * W;            // 16384
constexpr int NPIX = B * HW;           // 32768
constexpr int R2   = 256;              // 16x16 reduced K/V
constexpr int DH   = 32;               // dim_head
constexpr float BN_EPS = 1e-5f;
}

// ---------------- scratch (static device, no allocs) ----------------
__device__ float g_pool[B * C0 * HW];
__device__ float g_t   [B * C1 * HW];
__device__ float g_u   [B * C1 * HW];
__device__ float g_o   [B * C1 * HW];
__device__ float g_qkv [B * 3 * C1 * HW];
__device__ float g_kd  [B * C1 * R2];
__device__ float g_vd  [B * C1 * R2];
__device__ double2 g_part[128][4];           // BN partial sums
__device__ float g_A   [8 * 128];
__device__ float g_Bv  [8 * 128];

// ---------------- helpers ----------------
__device__ __forceinline__ unsigned f2tf(float x) {
    unsigned r;
    asm("cvt.rna.tf32.f32 %0, %1;" : "=r"(r) : "f"(x));
    return r;
}
__device__ __forceinline__ void mma8(float c[4], const unsigned a[4], const unsigned b[2]) {
    asm volatile(
        "mma.sync.aligned.m16n8k8.row.col.f32.tf32.tf32.f32 "
        "{%0,%1,%2,%3},{%4,%5,%6,%7},{%8,%9},{%0,%1,%2,%3};"
        : "+f"(c[0]), "+f"(c[1]), "+f"(c[2]), "+f"(c[3])
        : "r"(a[0]), "r"(a[1]), "r"(a[2]), "r"(a[3]), "r"(b[0]), "r"(b[1]));
}

// ---------------- maxpool 2x2 (256x256 -> 128x128) ----------------
__global__ void k_maxpool(const float* __restrict__ x, float* __restrict__ out) {
    int i = blockIdx.x * 256 + threadIdx.x;
    int p  = i & (HW - 1);
    int bc = i >> 14;
    int y = p >> 7, xx = p & 127;
    const float* ip = x + (size_t)bc * 65536 + (size_t)(y * 2) * 256 + xx * 2;
    out[i] = fmaxf(fmaxf(ip[0], ip[1]), fmaxf(ip[256], ip[257]));
}

// ---------------- BN stats phase 1: partial sums, grid (C, 4) ----------------
__global__ void k_bnpart(const float* __restrict__ x, int Cc) {
    int c = blockIdx.x, part = blockIdx.y;
    int tid = threadIdx.x;
    const float4* x0 = reinterpret_cast<const float4*>(x + (size_t)c * HW) + part * (HW / 16);
    const float4* x1 = reinterpret_cast<const float4*>(x + (size_t)(Cc + c) * HW) + part * (HW / 16);
    float s = 0.f, s2 = 0.f;
#pragma unroll
    for (int it = 0; it < 4; it++) {
        int p = tid + it * 256;
        float4 a = x0[p];
        s += a.x + a.y + a.z + a.w;
        s2 = fmaf(a.x, a.x, fmaf(a.y, a.y, fmaf(a.z, a.z, fmaf(a.w, a.w, s2))));
        float4 d = x1[p];
        s += d.x + d.y + d.z + d.w;
        s2 = fmaf(d.x, d.x, fmaf(d.y, d.y, fmaf(d.z, d.z, fmaf(d.w, d.w, s2))));
    }
    __shared__ double rs[256], rq[256];
    rs[tid] = (double)s; rq[tid] = (double)s2;
    __syncthreads();
    for (int off = 128; off > 0; off >>= 1) {
        if (tid < off) { rs[tid] += rs[tid + off]; rq[tid] += rq[tid + off]; }
        __syncthreads();
    }
    if (tid == 0) g_part[c][part] = make_double2(rs[0], rq[0]);
}

// ---------------- BN stats phase 2: finalize, 1 block ----------------
__global__ void k_bnfin(const float* __restrict__ gg, const float* __restrict__ bb,
                        int Cc, int slot) {
    int c = threadIdx.x;
    if (c >= Cc) return;
    double s = 0., s2 = 0.;
#pragma unroll
    for (int p = 0; p < 4; p++) { s += g_part[c][p].x; s2 += g_part[c][p].y; }
    double mean = s / (double)NPIX;
    double var  = s2 / (double)NPIX - mean * mean;
    double A    = (double)gg[c] / sqrt(var + (double)BN_EPS);
    g_A[slot * 128 + c]  = (float)A;
    g_Bv[slot * 128 + c] = (float)((double)bb[c] - mean * A);
}

// ---------------- tf32 GEMM, 2-stage pipelined ----------------
// C[M,N] = W[M,K] @ X[K,N] (+add). Block tile 128x128, 256 thr = 8 warps (m64 x n32).
// IC: implicit im2col (K = CIN*9, zero pad after BN/ReLU). BN/RELU on X. ADD: +=add.
template <int K, int CIN, bool IC, bool BN, bool RELU, bool ADD>
__global__ __launch_bounds__(256)
void k_gemm(const float* __restrict__ in, const float* __restrict__ w,
            float* __restrict__ out, const float* __restrict__ add,
            int COUT, int slot) {
    extern __shared__ unsigned smbuf[];
    unsigned* sA = smbuf;                 // [2][128*36]
    unsigned* sB = smbuf + 2 * 128 * 36;  // [2][32*136]

    const int tid = threadIdx.x;
    const int lane = tid & 31, warp = tid >> 5;
    const int gid = lane >> 2, qid = lane & 3;
    const int wm = (warp & 1) * 64, wn = (warp >> 1) * 32;

    const int n0 = blockIdx.x * 128;
    const int m0 = blockIdx.y * 128;
    const int b  = n0 >> 14;
    const int pbase = n0 & (HW - 1);
    const int y = pbase >> 7;

    const float* Ap = g_A  + slot * 128;
    const float* Bp = g_Bv + slot * 128;

    float c[4][4][4];
#pragma unroll
    for (int mt = 0; mt < 4; mt++)
#pragma unroll
        for (int nt = 0; nt < 4; nt++)
#pragma unroll
            for (int e = 0; e < 4; e++) c[mt][nt][e] = 0.f;

    const int a_col4 = (tid & 7) * 4;
    const int a_row0 = tid >> 3;
    const int b_col4 = (tid & 31) * 4;
    const int b_row0 = tid >> 5;

    float4 arv[4];
    float  brv[4][4];

    // ---- loaders: global -> regs ----
    auto loadA = [&](int k0) {
#pragma unroll
        for (int i = 0; i < 4; i++) {
            int row = a_row0 + 32 * i;
            arv[i] = *reinterpret_cast<const float4*>(
                w + (size_t)(m0 + row) * K + k0 + a_col4);
        }
    };
    auto loadB = [&](int k0) {
#pragma unroll
        for (int i = 0; i < 4; i++) {
            int k = k0 + b_row0 + 8 * i;
            if (IC) {
                int ci = k / 9, q = k - ci * 9;
                int dy = q / 3 - 1, dx = q - (q / 3) * 3 - 1;
                int gy = y + dy;
                const float* src = in + ((size_t)(b * CIN) + ci) * HW + gy * 128;
                bool yok = (unsigned)gy < 128u;
#pragma unroll
                for (int e = 0; e < 4; e++) {
                    int gx = b_col4 + dx + e;
                    brv[i][e] = (yok && (unsigned)gx < 128u) ? src[gx] : 0.f;
                }
            } else {
                float4 xv = *reinterpret_cast<const float4*>(
                    in + ((size_t)(b * CIN) + k) * HW + pbase + b_col4);
                brv[i][0] = xv.x; brv[i][1] = xv.y; brv[i][2] = xv.z; brv[i][3] = xv.w;
            }
        }
    };
    // ---- regs -> smem (with cvt, BN/ReLU on B) ----
    auto storeA = [&](int buf) {
        unsigned* base = sA + buf * (128 * 36);
#pragma unroll
        for (int i = 0; i < 4; i++) {
            unsigned* d = base + (a_row0 + 32 * i) * 36 + a_col4;
            d[0] = f2tf(arv[i].x); d[1] = f2tf(arv[i].y);
            d[2] = f2tf(arv[i].z); d[3] = f2tf(arv[i].w);
        }
    };
    auto storeB = [&](int buf, int k0) {
        unsigned* base = sB + buf * (32 * 136);
#pragma unroll
        for (int i = 0; i < 4; i++) {
            int r = b_row0 + 8 * i;
            int k = k0 + r;
            int ci = IC ? (k / 9) : k;
            float A = 1.f, Bb = 0.f;
            if (BN) { A = Ap[ci]; Bb = Bp[ci]; }
            unsigned* d = base + r * 136 + b_col4;
#pragma unroll
            for (int e = 0; e < 4; e++) {
                float v = brv[i][e];
                if (BN) {
                    // preserve zero-padding: pad elements were exactly 0 from loader,
                    // but BN shifts them; for IC we must re-zero out-of-range taps.
                    v = fmaf(v, A, Bb);
                    if (RELU) v = fmaxf(v, 0.f);
                    if (IC) {
                        int q = k - ci * 9;
                        int dy = q / 3 - 1, dx = q - (q / 3) * 3 - 1;
                        int gy = y + dy, gx = b_col4 + dx + e;
                        if (!((unsigned)gy < 128u && (unsigned)gx < 128u)) v = 0.f;
                    }
                }
                d[e] = f2tf(v);
            }
        }
    };

    constexpr int NC = K / 32;
    loadA(0); loadB(0);
    storeA(0); storeB(0, 0);
    __syncthreads();

    for (int ch = 0; ch < NC; ch++) {
        int buf = ch & 1;
        if (ch + 1 < NC) { loadA((ch + 1) * 32); loadB((ch + 1) * 32); }

        const unsigned* cA = sA + buf * (128 * 36);
        const unsigned* cB = sB + buf * (32 * 136);
#pragma unroll
        for (int ks = 0; ks < 4; ks++) {
            const int kk = ks * 8;
            unsigned af[4][4], bf[4][2];
#pragma unroll
            for (int mt = 0; mt < 4; mt++) {
                const unsigned* sa = cA + (wm + mt * 16 + gid) * 36 + kk + qid;
                af[mt][0] = sa[0];
                af[mt][1] = sa[8 * 36];
                af[mt][2] = sa[4];
                af[mt][3] = sa[8 * 36 + 4];
            }
#pragma unroll
            for (int nt = 0; nt < 4; nt++) {
                const unsigned* sb = cB + (kk + qid) * 136 + wn + nt * 8 + gid;
                bf[nt][0] = sb[0];
                bf[nt][1] = sb[4 * 136];
            }
#pragma unroll
            for (int mt = 0; mt < 4; mt++)
#pragma unroll
                for (int nt = 0; nt < 4; nt++)
                    mma8(c[mt][nt], af[mt], bf[nt]);
        }

        if (ch + 1 < NC) { storeA(buf ^ 1); storeB(buf ^ 1, (ch + 1) * 32); }
        __syncthreads();
    }

    // ---- epilogue ----
#pragma unroll
    for (int mt = 0; mt < 4; mt++) {
        int co = m0 + wm + mt * 16 + gid;
#pragma unroll
        for (int nt = 0; nt < 4; nt++) {
            int cb = wn + nt * 8 + qid * 2;
            size_t idx0 = ((size_t)(b * COUT) + co) * HW + pbase + cb;
            size_t idx1 = ((size_t)(b * COUT) + co + 8) * HW + pbase + cb;
            float2 r0 = make_float2(c[mt][nt][0], c[mt][nt][1]);
            float2 r1 = make_float2(c[mt][nt][2], c[mt][nt][3]);
            if (ADD) {
                float2 a0 = *reinterpret_cast<const float2*>(add + idx0);
                float2 a1 = *reinterpret_cast<const float2*>(add + idx1);
                r0.x += a0.x; r0.y += a0.y; r1.x += a1.x; r1.y += a1.y;
            }
            *reinterpret_cast<float2*>(out + idx0) = r0;
            *reinterpret_cast<float2*>(out + idx1) = r1;
        }
    }
}

// ---------------- depthwise 3x3, pad=1, optional fused BN ----------------
template <int BN>
__global__ void k_dw3(const float* __restrict__ in, const float* __restrict__ w,
                      float* __restrict__ out, int slot) {
    int i = blockIdx.x * 256 + threadIdx.x;
    int p  = i & (HW - 1);
    int bc = i >> 14;
    int c  = bc & 127;
    int y = p >> 7, x = p & 127;
    const float* ip = in + (size_t)bc * HW;
    const float* wp = w + c * 9;
    float A = 1.f, Bb = 0.f;
    if (BN) { A = g_A[slot * 128 + c]; Bb = g_Bv[slot * 128 + c]; }
    float s = 0.f;
#pragma unroll
    for (int dy = 0; dy < 3; dy++) {
        int gy = y + dy - 1;
        if ((unsigned)gy >= 128u) continue;
#pragma unroll
        for (int dx = 0; dx < 3; dx++) {
            int gx = x + dx - 1;
            if ((unsigned)gx >= 128u) continue;
            float v = ip[gy * 128 + gx];
            if (BN) v = fmaf(v, A, Bb);
            s = fmaf(v, wp[dy * 3 + dx], s);
        }
    }
    out[i] = s;
}

// ---------------- bilinear downsample k,v: 128x128 -> 16x16 ----------------
__global__ void k_ds(const float* __restrict__ qkv) {
    int i = blockIdx.x * 256 + threadIdx.x;
    int j  = i & 255;
    int oc = (i >> 8) & 255;
    int b  = i >> 16;
    const float* ip = qkv + ((size_t)(b * 384) + 128 + oc) * HW;
    int r = j >> 4, s = j & 15;
    const float step = (float)(127.0 / 15.0);
    float ph = (float)r * step;
    int   lh = min((int)ph, 126);
    float fh = ph - (float)lh;
    float pw = (float)s * step;
    int   lw = min((int)pw, 126);
    float fw = pw - (float)lw;
    const float* p0 = ip + lh * 128 + lw;
    float v00 = p0[0], v01 = p0[1], v10 = p0[128], v11 = p0[129];
    float val = (1.f - fh) * ((1.f - fw) * v00 + fw * v01)
              +        fh  * ((1.f - fw) * v10 + fw * v11);
    float* dst = (oc < 128) ? g_kd : g_vd;
    int cc = oc & 127;
    dst[(size_t)(b * 128 + cc) * R2 + j] = val;
}

// ---------------- fused attention: one thread per query pixel ----------------
__global__ void k_attn(const float* __restrict__ qkv, const float* __restrict__ table,
                       float* __restrict__ outp) {
    extern __shared__ float sm[];
    float* k_s = sm;
    float* v_s = sm + R2 * DH;
    float* t_s = sm + 2 * R2 * DH;
    int tid = threadIdx.x;
    int bh  = blockIdx.y;
    int b = bh >> 2, head = bh & 3;
    const float scale = 0.17677669529663687f;
    for (int i = tid; i < R2 * DH; i += 256) {
        int d = i >> 8, j = i & 255;
        k_s[j * DH + d] = g_kd[((size_t)(b * C1) + d * 4 + head) * R2 + j];
        v_s[j * DH + d] = g_vd[((size_t)(b * C1) + d * 4 + head) * R2 + j];
    }
    for (int i = tid; i < 961; i += 256) t_s[i] = table[i * 4 + head] * scale;
    __syncthreads();

    int p = blockIdx.x * 256 + tid;
    float q[DH];
#pragma unroll
    for (int d = 0; d < DH; d++)
        q[d] = qkv[((size_t)(b * 384) + d * 4 + head) * HW + p] * scale;
    int rh = p >> 10;
    int rw = (p >> 3) & 15;
    float l = 0.f;
    float o[DH];
#pragma unroll
    for (int d = 0; d < DH; d++) o[d] = 0.f;

    for (int j = 0; j < 256; j++) {
        int jh = j >> 4, jw = j & 15;
        float bias = t_s[(rh - jh + 15) * 31 + (rw - jw + 15)];
        const float4* k4 = reinterpret_cast<const float4*>(k_s + j * DH);
        float s = bias;
#pragma unroll
        for (int t = 0; t < 8; t++) {
            float4 kv = k4[t];
            s = fmaf(q[4 * t], kv.x, s);
            s = fmaf(q[4 * t + 1], kv.y, s);
            s = fmaf(q[4 * t + 2], kv.z, s);
            s = fmaf(q[4 * t + 3], kv.w, s);
        }
        float e = __expf(s);
        l += e;
        const float4* v4 = reinterpret_cast<const float4*>(v_s + j * DH);
#pragma unroll
        for (int t = 0; t < 8; t++) {
            float4 vv = v4[t];
            o[4 * t]     = fmaf(e, vv.x, o[4 * t]);
            o[4 * t + 1] = fmaf(e, vv.y, o[4 * t + 1]);
            o[4 * t + 2] = fmaf(e, vv.z, o[4 * t + 2]);
            o[4 * t + 3] = fmaf(e, vv.w, o[4 * t + 3]);
        }
    }
    float inv = 1.f / l;
#pragma unroll
    for (int d = 0; d < DH; d++)
        outp[((size_t)(b * C1) + d * 4 + head) * HW + p] = o[d] * inv;
}

// ---------------- host orchestration ----------------
extern "C" void kernel_launch(void* const* d_in, const int* in_sizes, int n_in,
                              void* d_out, int out_size) {
    (void)in_sizes; (void)n_in; (void)out_size;
    const float* x        = (const float*)d_in[0];
    const float* bb_bn1_g = (const float*)d_in[1];
    const float* bb_bn1_b = (const float*)d_in[2];
    const float* bb_conv1 = (const float*)d_in[3];
    const float* bb_bn2_g = (const float*)d_in[4];
    const float* bb_bn2_b = (const float*)d_in[5];
    const float* bb_conv2 = (const float*)d_in[6];
    const float* bb_sbn_g = (const float*)d_in[7];
    const float* bb_sbn_b = (const float*)d_in[8];
    const float* bb_sconv = (const float*)d_in[9];
    const float* tb_bn1_g = (const float*)d_in[10];
    const float* tb_bn1_b = (const float*)d_in[11];
    const float* tb_dwqkv = (const float*)d_in[12];
    const float* tb_pwqkv = (const float*)d_in[13];
    const float* tb_dwout = (const float*)d_in[14];
    const float* tb_pwout = (const float*)d_in[15];
    const float* tb_rel   = (const float*)d_in[16];
    const float* tb_bn2_g = (const float*)d_in[17];
    const float* tb_bn2_b = (const float*)d_in[18];
    const float* tb_mlp   = (const float*)d_in[19];

    void* pv;
    float *pool, *t, *u, *o, *qkv;
    cudaGetSymbolAddress(&pv, g_pool); pool = (float*)pv;
    cudaGetSymbolAddress(&pv, g_t);    t    = (float*)pv;
    cudaGetSymbolAddress(&pv, g_u);    u    = (float*)pv;
    cudaGetSymbolAddress(&pv, g_o);    o    = (float*)pv;
    cudaGetSymbolAddress(&pv, g_qkv);  qkv  = (float*)pv;

    const int GEMM_SMEM = (2 * 128 * 36 + 2 * 32 * 136) * 4;  // 71680
    const int ATTN_SMEM = (2 * R2 * DH + 961) * 4;
    cudaFuncSetAttribute(k_gemm<576, 64, true, true, true, false>,
                         cudaFuncAttributeMaxDynamicSharedMemorySize, GEMM_SMEM);
    cudaFuncSetAttribute(k_gemm<1152, 128, true, true, true, false>,
                         cudaFuncAttributeMaxDynamicSharedMemorySize, GEMM_SMEM);
    cudaFuncSetAttribute(k_gemm<64, 64, false, true, true, true>,
                         cudaFuncAttributeMaxDynamicSharedMemorySize, GEMM_SMEM);
    cudaFuncSetAttribute(k_gemm<128, 128, false, false, false, false>,
                         cudaFuncAttributeMaxDynamicSharedMemorySize, GEMM_SMEM);
    cudaFuncSetAttribute(k_gemm<128, 128, false, false, false, true>,
                         cudaFuncAttributeMaxDynamicSharedMemorySize, GEMM_SMEM);
    cudaFuncSetAttribute(k_gemm<128, 128, false, true, true, true>,
                         cudaFuncAttributeMaxDynamicSharedMemorySize, GEMM_SMEM);
    cudaFuncSetAttribute(k_attn, cudaFuncAttributeMaxDynamicSharedMemorySize, 71680);

    const dim3 g1(NPIX / 128, 1);
    const dim3 g3(NPIX / 128, 3);

    k_maxpool<<<(B * C0 * HW) / 256, 256>>>(x, pool);

    // ---- BasicBlock ----
    k_bnpart<<<dim3(C0, 4), 256>>>(pool, C0);
    k_bnfin<<<1, 128>>>(bb_bn1_g, bb_bn1_b, C0, 0);
    k_gemm<576, 64, true, true, true, false><<<g1, 256, GEMM_SMEM>>>(pool, bb_conv1, u, nullptr, 128, 0);
    k_bnpart<<<dim3(C1, 4), 256>>>(u, C1);
    k_bnfin<<<1, 128>>>(bb_bn2_g, bb_bn2_b, C1, 1);
    k_gemm<1152, 128, true, true, true, false><<<g1, 256, GEMM_SMEM>>>(u, bb_conv2, o, nullptr, 128, 1);
    k_bnpart<<<dim3(C0, 4), 256>>>(pool, C0);
    k_bnfin<<<1, 128>>>(bb_sbn_g, bb_sbn_b, C0, 2);
    k_gemm<64, 64, false, true, true, true><<<g1, 256, GEMM_SMEM>>>(pool, bb_sconv, o, o, 128, 2);

    // ---- 2 x BasicTransBlock (ping-pong residual between o and t) ----
    float* ob = o;
    float* tb = t;
    for (int i = 0; i < 2; i++) {
        k_bnpart<<<dim3(C1, 4), 256>>>(ob, C1);
        k_bnfin<<<1, 128>>>(tb_bn1_g + i * 128, tb_bn1_b + i * 128, C1, 3);
        k_dw3<1><<<(B * C1 * HW) / 256, 256>>>(ob, tb_dwqkv + (size_t)i * 128 * 9, u, 3);
        k_gemm<128, 128, false, false, false, false><<<g3, 256, GEMM_SMEM>>>(
            u, tb_pwqkv + (size_t)i * 384 * 128, qkv, nullptr, 384, 0);
        k_ds<<<(B * 256 * R2) / 256, 256>>>(qkv);
        k_attn<<<dim3(HW / 256, B * 4), 256, ATTN_SMEM>>>(
            qkv, tb_rel + (size_t)i * 961 * 4, tb);
        k_dw3<0><<<(B * C1 * HW) / 256, 256>>>(tb, tb_dwout + (size_t)i * 128 * 9, u, 0);
        k_gemm<128, 128, false, false, false, true><<<g1, 256, GEMM_SMEM>>>(
            u, tb_pwout + (size_t)i * 128 * 128, ob, ob, 128, 0);
        k_bnpart<<<dim3(C1, 4), 256>>>(ob, C1);
        k_bnfin<<<1, 128>>>(tb_bn2_g + i * 128, tb_bn2_b + i * 128, C1, 4);
        float* dest = (i == 1) ? (float*)d_out : tb;
        k_gemm<128, 128, false, true, true, true><<<g1, 256, GEMM_SMEM>>>(
            ob, tb_mlp + (size_t)i * 128 * 128, dest, ob, 128, 4);
        float* tmp = ob; ob = tb; tb = tmp;
    }
}

// round 5
// speedup vs baseline: 1.2475x; 1.2475x over previous
#include <cuda_runtime.h>
#include <cstdint>

// ---------------- problem constants ----------------
namespace {
constexpr int B    = 2;
constexpr int C0   = 64;
constexpr int C1   = 128;
constexpr int H    = 128, W = 128;
constexpr int HW   = H * W;            // 16384
constexpr int NPIX = B * HW;           // 32768
constexpr int R2   = 256;              // 16x16 reduced K/V
constexpr int DH   = 32;               // dim_head
constexpr float BN_EPS = 1e-5f;
}

// ---------------- scratch (static device, no allocs) ----------------
__device__ float g_pool[B * C0 * HW];
__device__ float g_t   [B * C1 * HW];
__device__ float g_u   [B * C1 * HW];
__device__ float g_o   [B * C1 * HW];
__device__ float g_qkv [B * 3 * C1 * HW];
__device__ float g_kd  [B * C1 * R2];
__device__ float g_vd  [B * C1 * R2];
__device__ double2 g_part[128][4];           // BN partial sums
__device__ float g_A   [8 * 128];
__device__ float g_Bv  [8 * 128];

// ---------------- helpers ----------------
__device__ __forceinline__ unsigned f2tf(float x) {
    unsigned r;
    asm("cvt.rna.tf32.f32 %0, %1;" : "=r"(r) : "f"(x));
    return r;
}
__device__ __forceinline__ void mma8(float c[4], const unsigned a[4], const unsigned b[2]) {
    asm volatile(
        "mma.sync.aligned.m16n8k8.row.col.f32.tf32.tf32.f32 "
        "{%0,%1,%2,%3},{%4,%5,%6,%7},{%8,%9},{%0,%1,%2,%3};"
        : "+f"(c[0]), "+f"(c[1]), "+f"(c[2]), "+f"(c[3])
        : "r"(a[0]), "r"(a[1]), "r"(a[2]), "r"(a[3]), "r"(b[0]), "r"(b[1]));
}

// ---------------- maxpool 2x2 (256x256 -> 128x128) ----------------
__global__ void k_maxpool(const float* __restrict__ x, float* __restrict__ out) {
    int i = blockIdx.x * 256 + threadIdx.x;
    int p  = i & (HW - 1);
    int bc = i >> 14;
    int y = p >> 7, xx = p & 127;
    const float* ip = x + (size_t)bc * 65536 + (size_t)(y * 2) * 256 + xx * 2;
    out[i] = fmaxf(fmaxf(ip[0], ip[1]), fmaxf(ip[256], ip[257]));
}

// ---------------- BN stats phase 1: partial sums, grid (C, 4) ----------------
__global__ void k_bnpart(const float* __restrict__ x, int Cc) {
    int c = blockIdx.x, part = blockIdx.y;
    int tid = threadIdx.x;
    const float4* x0 = reinterpret_cast<const float4*>(x + (size_t)c * HW) + part * (HW / 16);
    const float4* x1 = reinterpret_cast<const float4*>(x + (size_t)(Cc + c) * HW) + part * (HW / 16);
    float s = 0.f, s2 = 0.f;
#pragma unroll
    for (int it = 0; it < 4; it++) {
        int p = tid + it * 256;
        float4 a = x0[p];
        s += a.x + a.y + a.z + a.w;
        s2 = fmaf(a.x, a.x, fmaf(a.y, a.y, fmaf(a.z, a.z, fmaf(a.w, a.w, s2))));
        float4 d = x1[p];
        s += d.x + d.y + d.z + d.w;
        s2 = fmaf(d.x, d.x, fmaf(d.y, d.y, fmaf(d.z, d.z, fmaf(d.w, d.w, s2))));
    }
    __shared__ double rs[256], rq[256];
    rs[tid] = (double)s; rq[tid] = (double)s2;
    __syncthreads();
    for (int off = 128; off > 0; off >>= 1) {
        if (tid < off) { rs[tid] += rs[tid + off]; rq[tid] += rq[tid + off]; }
        __syncthreads();
    }
    if (tid == 0) g_part[c][part] = make_double2(rs[0], rq[0]);
}

// ---------------- BN stats phase 2: finalize, 1 block ----------------
__global__ void k_bnfin(const float* __restrict__ gg, const float* __restrict__ bb,
                        int Cc, int slot) {
    int c = threadIdx.x;
    if (c >= Cc) return;
    double s = 0., s2 = 0.;
#pragma unroll
    for (int p = 0; p < 4; p++) { s += g_part[c][p].x; s2 += g_part[c][p].y; }
    double mean = s / (double)NPIX;
    double var  = s2 / (double)NPIX - mean * mean;
    double A    = (double)gg[c] / sqrt(var + (double)BN_EPS);
    g_A[slot * 128 + c]  = (float)A;
    g_Bv[slot * 128 + c] = (float)((double)bb[c] - mean * A);
}

// ---------------- tf32 GEMM (round-3 form: single buffer, 2 CTA/SM) ----------
template <int K, int CIN, bool IC, bool BN, bool RELU, bool ADD>
__global__ __launch_bounds__(256)
void k_gemm(const float* __restrict__ in, const float* __restrict__ w,
            float* __restrict__ out, const float* __restrict__ add,
            int COUT, int slot) {
    __shared__ unsigned sA[128 * 36];     // [row][k] stride 36
    __shared__ unsigned sB[32 * 136];     // [k][n]  stride 136

    const int tid = threadIdx.x;
    const int lane = tid & 31, warp = tid >> 5;
    const int gid = lane >> 2, qid = lane & 3;
    const int wm = (warp & 1) * 64, wn = (warp >> 1) * 32;

    const int n0 = blockIdx.x * 128;
    const int m0 = blockIdx.y * 128;
    const int b  = n0 >> 14;
    const int pbase = n0 & (HW - 1);
    const int y = pbase >> 7;

    const float* Ap = g_A  + slot * 128;
    const float* Bp = g_Bv + slot * 128;

    float c[4][4][4];
#pragma unroll
    for (int mt = 0; mt < 4; mt++)
#pragma unroll
        for (int nt = 0; nt < 4; nt++)
#pragma unroll
            for (int e = 0; e < 4; e++) c[mt][nt][e] = 0.f;

    const int a_col4 = (tid & 7) * 4;
    const int a_row0 = tid >> 3;
    const int b_col4 = (tid & 31) * 4;
    const int b_row0 = tid >> 5;

    for (int k0 = 0; k0 < K; k0 += 32) {
        __syncthreads();
#pragma unroll
        for (int i = 0; i < 4; i++) {
            int row = a_row0 + 32 * i;
            const float4 wv = *reinterpret_cast<const float4*>(
                w + (size_t)(m0 + row) * K + k0 + a_col4);
            unsigned* d = sA + row * 36 + a_col4;
            d[0] = f2tf(wv.x); d[1] = f2tf(wv.y); d[2] = f2tf(wv.z); d[3] = f2tf(wv.w);
        }
#pragma unroll
        for (int i = 0; i < 4; i++) {
            int r = b_row0 + 8 * i;
            int k = k0 + r;
            unsigned* d = sB + r * 136 + b_col4;
            if (IC) {
                int ci = k / 9, q = k - ci * 9;
                int dy = q / 3 - 1, dx = q - (q / 3) * 3 - 1;
                int gy = y + dy;
                float A = 1.f, Bb = 0.f;
                if (BN) { A = Ap[ci]; Bb = Bp[ci]; }
                const float* src = in + ((size_t)(b * CIN) + ci) * HW + gy * 128;
                bool yok = (unsigned)gy < 128u;
#pragma unroll
                for (int e = 0; e < 4; e++) {
                    int gx = b_col4 + dx + e;
                    float v = 0.f;
                    if (yok && (unsigned)gx < 128u) {
                        v = src[gx];
                        if (BN) v = fmaf(v, A, Bb);
                        if (RELU) v = fmaxf(v, 0.f);
                    }
                    d[e] = f2tf(v);
                }
            } else {
                float4 xv = *reinterpret_cast<const float4*>(
                    in + ((size_t)(b * CIN) + k) * HW + pbase + b_col4);
                if (BN) {
                    float A = Ap[k], Bb = Bp[k];
                    xv.x = fmaf(xv.x, A, Bb); xv.y = fmaf(xv.y, A, Bb);
                    xv.z = fmaf(xv.z, A, Bb); xv.w = fmaf(xv.w, A, Bb);
                    if (RELU) {
                        xv.x = fmaxf(xv.x, 0.f); xv.y = fmaxf(xv.y, 0.f);
                        xv.z = fmaxf(xv.z, 0.f); xv.w = fmaxf(xv.w, 0.f);
                    }
                }
                d[0] = f2tf(xv.x); d[1] = f2tf(xv.y); d[2] = f2tf(xv.z); d[3] = f2tf(xv.w);
            }
        }
        __syncthreads();
#pragma unroll
        for (int ks = 0; ks < 4; ks++) {
            const int kk = ks * 8;
            unsigned af[4][4], bf[4][2];
#pragma unroll
            for (int mt = 0; mt < 4; mt++) {
                const unsigned* sa = sA + (wm + mt * 16 + gid) * 36 + kk + qid;
                af[mt][0] = sa[0];
                af[mt][1] = sa[8 * 36];
                af[mt][2] = sa[4];
                af[mt][3] = sa[8 * 36 + 4];
            }
#pragma unroll
            for (int nt = 0; nt < 4; nt++) {
                const unsigned* sb = sB + (kk + qid) * 136 + wn + nt * 8 + gid;
                bf[nt][0] = sb[0];
                bf[nt][1] = sb[4 * 136];
            }
#pragma unroll
            for (int mt = 0; mt < 4; mt++)
#pragma unroll
                for (int nt = 0; nt < 4; nt++)
                    mma8(c[mt][nt], af[mt], bf[nt]);
        }
    }

#pragma unroll
    for (int mt = 0; mt < 4; mt++) {
        int co = m0 + wm + mt * 16 + gid;
#pragma unroll
        for (int nt = 0; nt < 4; nt++) {
            int cb = wn + nt * 8 + qid * 2;
            size_t idx0 = ((size_t)(b * COUT) + co) * HW + pbase + cb;
            size_t idx1 = ((size_t)(b * COUT) + co + 8) * HW + pbase + cb;
            float2 r0 = make_float2(c[mt][nt][0], c[mt][nt][1]);
            float2 r1 = make_float2(c[mt][nt][2], c[mt][nt][3]);
            if (ADD) {
                float2 a0 = *reinterpret_cast<const float2*>(add + idx0);
                float2 a1 = *reinterpret_cast<const float2*>(add + idx1);
                r0.x += a0.x; r0.y += a0.y; r1.x += a1.x; r1.y += a1.y;
            }
            *reinterpret_cast<float2*>(out + idx0) = r0;
            *reinterpret_cast<float2*>(out + idx1) = r1;
        }
    }
}

// ---------------- depthwise 3x3, pad=1, optional fused BN ----------------
template <int BN>
__global__ void k_dw3(const float* __restrict__ in, const float* __restrict__ w,
                      float* __restrict__ out, int slot) {
    int i = blockIdx.x * 256 + threadIdx.x;
    int p  = i & (HW - 1);
    int bc = i >> 14;
    int c  = bc & 127;
    int y = p >> 7, x = p & 127;
    const float* ip = in + (size_t)bc * HW;
    const float* wp = w + c * 9;
    float A = 1.f, Bb = 0.f;
    if (BN) { A = g_A[slot * 128 + c]; Bb = g_Bv[slot * 128 + c]; }
    float s = 0.f;
#pragma unroll
    for (int dy = 0; dy < 3; dy++) {
        int gy = y + dy - 1;
        if ((unsigned)gy >= 128u) continue;
#pragma unroll
        for (int dx = 0; dx < 3; dx++) {
            int gx = x + dx - 1;
            if ((unsigned)gx >= 128u) continue;
            float v = ip[gy * 128 + gx];
            if (BN) v = fmaf(v, A, Bb);
            s = fmaf(v, wp[dy * 3 + dx], s);
        }
    }
    out[i] = s;
}

// ---------------- bilinear downsample k,v: 128x128 -> 16x16 ----------------
__global__ void k_ds(const float* __restrict__ qkv) {
    int i = blockIdx.x * 256 + threadIdx.x;
    int j  = i & 255;
    int oc = (i >> 8) & 255;
    int b  = i >> 16;
    const float* ip = qkv + ((size_t)(b * 384) + 128 + oc) * HW;
    int r = j >> 4, s = j & 15;
    const float step = (float)(127.0 / 15.0);
    float ph = (float)r * step;
    int   lh = min((int)ph, 126);
    float fh = ph - (float)lh;
    float pw = (float)s * step;
    int   lw = min((int)pw, 126);
    float fw = pw - (float)lw;
    const float* p0 = ip + lh * 128 + lw;
    float v00 = p0[0], v01 = p0[1], v10 = p0[128], v11 = p0[129];
    float val = (1.f - fh) * ((1.f - fw) * v00 + fw * v01)
              +        fh  * ((1.f - fw) * v10 + fw * v11);
    float* dst = (oc < 128) ? g_kd : g_vd;
    int cc = oc & 127;
    dst[(size_t)(b * 128 + cc) * R2 + j] = val;
}

// ---------------- tensor-core attention ----------------
// CTA = 128 threads (4 warps), 64 query px, all 256 KV.
// Warp w: rows w*16..w*16+15. S accum 16x256/warp. tf32 mma for QK and AV.
__global__ __launch_bounds__(128)
void k_attn(const float* __restrict__ qkv, const float* __restrict__ table,
            float* __restrict__ outp) {
    extern __shared__ unsigned smu[];
    unsigned* k_s = smu;                    // [256][36]
    unsigned* v_s = smu + 256 * 36;         // [256][36]
    unsigned* q_s = v_s + 256 * 36;         // [64][36]
    float*    t_s = reinterpret_cast<float*>(q_s + 64 * 36);   // [961] pre-scaled

    const int tid  = threadIdx.x;
    const int lane = tid & 31, warp = tid >> 5;
    const int gid  = lane >> 2, qid = lane & 3;
    const int bh   = blockIdx.y;
    const int b = bh >> 2, head = bh & 3;
    const int px0 = blockIdx.x * 64;
    const float scale = 0.17677669529663687f;   // 32^-0.5

    // ---- stage K, V (tf32), Q (pre-scaled tf32), bias table ----
    for (int i = tid; i < 256 * 32; i += 128) {
        int j = i & 255, d = i >> 8;
        size_t gi = ((size_t)(b * C1) + d * 4 + head) * R2 + j;
        k_s[j * 36 + d] = f2tf(g_kd[gi]);
        v_s[j * 36 + d] = f2tf(g_vd[gi]);
    }
    for (int i = tid; i < 64 * 32; i += 128) {
        int r = i & 63, d = i >> 6;
        q_s[r * 36 + d] = f2tf(qkv[((size_t)(b * 384) + d * 4 + head) * HW + px0 + r] * scale);
    }
    for (int i = tid; i < 961; i += 128) t_s[i] = table[i * 4 + head] * scale;
    __syncthreads();

    // ---- QK^T: S[16][256] per warp ----
    unsigned aq[4][4];
#pragma unroll
    for (int kc = 0; kc < 4; kc++) {
        const unsigned* sa = q_s + (warp * 16 + gid) * 36 + kc * 8 + qid;
        aq[kc][0] = sa[0];
        aq[kc][1] = sa[8 * 36];
        aq[kc][2] = sa[4];
        aq[kc][3] = sa[8 * 36 + 4];
    }
    float s[32][4];
#pragma unroll
    for (int nt = 0; nt < 32; nt++) { s[nt][0]=s[nt][1]=s[nt][2]=s[nt][3]=0.f; }
#pragma unroll
    for (int nt = 0; nt < 32; nt++) {
        const unsigned* kb = k_s + (nt * 8 + gid) * 36;
#pragma unroll
        for (int kc = 0; kc < 4; kc++) {
            unsigned bf[2];
            bf[0] = kb[kc * 8 + qid];
            bf[1] = kb[kc * 8 + qid + 4];
            mma8(s[nt], aq[kc], bf);
        }
    }

    // ---- bias + exp + row sums ----
    const int xb = (px0 & 127) + warp * 16;
    const int rh = (px0 >> 7) >> 3;
    const int base0 = (rh + 15) * 31 + ((xb + gid) >> 3) + 15;
    const int base1 = (rh + 15) * 31 + ((xb + gid + 8) >> 3) + 15;
    float l0 = 0.f, l1 = 0.f;
#pragma unroll
    for (int nt = 0; nt < 32; nt++) {
        int j = nt * 8 + 2 * qid;
        int off = (j >> 4) * 31 + (j & 15);
        float e0 = __expf(s[nt][0] + t_s[base0 - off]);
        float e1 = __expf(s[nt][1] + t_s[base0 - off - 1]);
        float e2 = __expf(s[nt][2] + t_s[base1 - off]);
        float e3 = __expf(s[nt][3] + t_s[base1 - off - 1]);
        s[nt][0] = e0; s[nt][1] = e1; s[nt][2] = e2; s[nt][3] = e3;
        l0 += e0 + e1; l1 += e2 + e3;
    }
    l0 += __shfl_xor_sync(0xffffffffu, l0, 1);
    l0 += __shfl_xor_sync(0xffffffffu, l0, 2);
    l1 += __shfl_xor_sync(0xffffffffu, l1, 1);
    l1 += __shfl_xor_sync(0xffffffffu, l1, 2);
    const float inv0 = 1.f / l0, inv1 = 1.f / l1;

    // ---- AV: O[16][32] per warp; P regs -> A frags via shfl ----
    float o[4][4];
#pragma unroll
    for (int nt = 0; nt < 4; nt++) { o[nt][0]=o[nt][1]=o[nt][2]=o[nt][3]=0.f; }
    const int src0 = (lane & ~3) | (qid >> 1);
    const int src1 = src0 + 2;
    const bool odd = (qid & 1);
#pragma unroll
    for (int kc = 0; kc < 32; kc++) {
        float p0 = s[kc][0], p1 = s[kc][1], p2 = s[kc][2], p3 = s[kc][3];
        float v00 = __shfl_sync(0xffffffffu, p0, src0);
        float v01 = __shfl_sync(0xffffffffu, p1, src0);
        float v10 = __shfl_sync(0xffffffffu, p2, src0);
        float v11 = __shfl_sync(0xffffffffu, p3, src0);
        float v20 = __shfl_sync(0xffffffffu, p0, src1);
        float v21 = __shfl_sync(0xffffffffu, p1, src1);
        float v30 = __shfl_sync(0xffffffffu, p2, src1);
        float v31 = __shfl_sync(0xffffffffu, p3, src1);
        unsigned a[4];
        a[0] = f2tf(odd ? v01 : v00);
        a[1] = f2tf(odd ? v11 : v10);
        a[2] = f2tf(odd ? v21 : v20);
        a[3] = f2tf(odd ? v31 : v30);
        const unsigned* vb0 = v_s + (kc * 8 + qid) * 36;
        const unsigned* vb1 = v_s + (kc * 8 + qid + 4) * 36;
#pragma unroll
        for (int ntd = 0; ntd < 4; ntd++) {
            unsigned bf[2];
            bf[0] = vb0[ntd * 8 + gid];
            bf[1] = vb1[ntd * 8 + gid];
            mma8(o[ntd], a, bf);
        }
    }

    // ---- epilogue: normalize rows and store ----
    const int px = px0 + warp * 16 + gid;
#pragma unroll
    for (int ntd = 0; ntd < 4; ntd++) {
        int d = ntd * 8 + 2 * qid;
        size_t c0 = ((size_t)(b * C1) + d * 4 + head) * HW;
        size_t c1 = ((size_t)(b * C1) + (d + 1) * 4 + head) * HW;
        outp[c0 + px]     = o[ntd][0] * inv0;
        outp[c1 + px]     = o[ntd][1] * inv0;
        outp[c0 + px + 8] = o[ntd][2] * inv1;
        outp[c1 + px + 8] = o[ntd][3] * inv1;
    }
}

// ---------------- host orchestration ----------------
extern "C" void kernel_launch(void* const* d_in, const int* in_sizes, int n_in,
                              void* d_out, int out_size) {
    (void)in_sizes; (void)n_in; (void)out_size;
    const float* x        = (const float*)d_in[0];
    const float* bb_bn1_g = (const float*)d_in[1];
    const float* bb_bn1_b = (const float*)d_in[2];
    const float* bb_conv1 = (const float*)d_in[3];
    const float* bb_bn2_g = (const float*)d_in[4];
    const float* bb_bn2_b = (const float*)d_in[5];
    const float* bb_conv2 = (const float*)d_in[6];
    const float* bb_sbn_g = (const float*)d_in[7];
    const float* bb_sbn_b = (const float*)d_in[8];
    const float* bb_sconv = (const float*)d_in[9];
    const float* tb_bn1_g = (const float*)d_in[10];
    const float* tb_bn1_b = (const float*)d_in[11];
    const float* tb_dwqkv = (const float*)d_in[12];
    const float* tb_pwqkv = (const float*)d_in[13];
    const float* tb_dwout = (const float*)d_in[14];
    const float* tb_pwout = (const float*)d_in[15];
    const float* tb_rel   = (const float*)d_in[16];
    const float* tb_bn2_g = (const float*)d_in[17];
    const float* tb_bn2_b = (const float*)d_in[18];
    const float* tb_mlp   = (const float*)d_in[19];

    void* pv;
    float *pool, *t, *u, *o, *qkv;
    cudaGetSymbolAddress(&pv, g_pool); pool = (float*)pv;
    cudaGetSymbolAddress(&pv, g_t);    t    = (float*)pv;
    cudaGetSymbolAddress(&pv, g_u);    u    = (float*)pv;
    cudaGetSymbolAddress(&pv, g_o);    o    = (float*)pv;
    cudaGetSymbolAddress(&pv, g_qkv);  qkv  = (float*)pv;

    const int ATTN_SMEM = (2 * 256 * 36 + 64 * 36) * 4 + 961 * 4;   // 86788
    cudaFuncSetAttribute(k_attn, cudaFuncAttributeMaxDynamicSharedMemorySize, ATTN_SMEM);

    const dim3 g1(NPIX / 128, 1);
    const dim3 g3(NPIX / 128, 3);
    const dim3 ga(HW / 64, B * 4);

    k_maxpool<<<(B * C0 * HW) / 256, 256>>>(x, pool);

    // ---- BasicBlock ----
    k_bnpart<<<dim3(C0, 4), 256>>>(pool, C0);
    k_bnfin<<<1, 128>>>(bb_bn1_g, bb_bn1_b, C0, 0);
    k_gemm<576, 64, true, true, true, false><<<g1, 256>>>(pool, bb_conv1, u, nullptr, 128, 0);
    k_bnpart<<<dim3(C1, 4), 256>>>(u, C1);
    k_bnfin<<<1, 128>>>(bb_bn2_g, bb_bn2_b, C1, 1);
    k_gemm<1152, 128, true, true, true, false><<<g1, 256>>>(u, bb_conv2, o, nullptr, 128, 1);
    k_bnpart<<<dim3(C0, 4), 256>>>(pool, C0);
    k_bnfin<<<1, 128>>>(bb_sbn_g, bb_sbn_b, C0, 2);
    k_gemm<64, 64, false, true, true, true><<<g1, 256>>>(pool, bb_sconv, o, o, 128, 2);

    // ---- 2 x BasicTransBlock (ping-pong residual between o and t) ----
    float* ob = o;
    float* tb = t;
    for (int i = 0; i < 2; i++) {
        k_bnpart<<<dim3(C1, 4), 256>>>(ob, C1);
        k_bnfin<<<1, 128>>>(tb_bn1_g + i * 128, tb_bn1_b + i * 128, C1, 3);
        k_dw3<1><<<(B * C1 * HW) / 256, 256>>>(ob, tb_dwqkv + (size_t)i * 128 * 9, u, 3);
        k_gemm<128, 128, false, false, false, false><<<g3, 256>>>(
            u, tb_pwqkv + (size_t)i * 384 * 128, qkv, nullptr, 384, 0);
        k_ds<<<(B * 256 * R2) / 256, 256>>>(qkv);
        k_attn<<<ga, 128, ATTN_SMEM>>>(qkv, tb_rel + (size_t)i * 961 * 4, tb);
        k_dw3<0><<<(B * C1 * HW) / 256, 256>>>(tb, tb_dwout + (size_t)i * 128 * 9, u, 0);
        k_gemm<128, 128, false, false, false, true><<<g1, 256>>>(
            u, tb_pwout + (size_t)i * 128 * 128, ob, ob, 128, 0);
        k_bnpart<<<dim3(C1, 4), 256>>>(ob, C1);
        k_bnfin<<<1, 128>>>(tb_bn2_g + i * 128, tb_bn2_b + i * 128, C1, 4);
        float* dest = (i == 1) ? (float*)d_out : tb;
        k_gemm<128, 128, false, true, true, true><<<g1, 256>>>(
            ob, tb_mlp + (size_t)i * 128 * 128, dest, ob, 128, 4);
        float* tmp = ob; ob = tb; tb = tmp;
    }
}